// round 2
// baseline (speedup 1.0000x reference)
#include <cuda_runtime.h>

// ---------------------------------------------------------------------------
// GRU_23407571764060: 2-layer GRU (B=4096, L=128, in=16, hid=128) + FC(128->24)
//
// Strategy:
//  - prep kernel: transpose the 4 weight matrices into [k][g] layout so the
//    recurrent-matvec weight loads are lane-coalesced.
//  - main kernel: 256 CTAs x 384 threads; each CTA owns MB=16 samples.
//    h1/h2 state in SMEM as [k][m] (m minor) so gate threads read 4 samples
//    per broadcast LDS.128, consumed as two f32x2 operands.
//    Thread g computes gate-row g for all 16 samples with packed fma.rn.f32x2
//    (fp32 precision, 2 MAC/inst).
// ---------------------------------------------------------------------------

#define MB    16      // samples per CTA
#define G3    384     // 3*HIDDEN gate rows
#define HID   128
#define LSEQ  128
#define NCLS  24

// transposed weight scratch (written by prep kernel every call; deterministic)
__device__ float g_wih1T[16  * G3];
__device__ float g_whh1T[HID * G3];
__device__ float g_wih2T[HID * G3];
__device__ float g_whh2T[HID * G3];

// ---- f32x2 helpers --------------------------------------------------------
__device__ __forceinline__ void fma2(unsigned long long& acc,
                                     unsigned long long a,
                                     unsigned long long b) {
    asm("fma.rn.f32x2 %0, %1, %2, %0;" : "+l"(acc) : "l"(a), "l"(b));
}
__device__ __forceinline__ unsigned long long pack2(float x) {
    unsigned long long r;
    unsigned u = __float_as_uint(x);
    asm("mov.b64 %0, {%1, %1};" : "=l"(r) : "r"(u));
    return r;
}
__device__ __forceinline__ float2 unpack2(unsigned long long v) {
    unsigned lo, hi;
    asm("mov.b64 {%0, %1}, %2;" : "=r"(lo), "=r"(hi) : "l"(v));
    return make_float2(__uint_as_float(lo), __uint_as_float(hi));
}

__device__ __forceinline__ float sigf(float x) {
    return 1.0f / (1.0f + __expf(-x));   // x<<0 -> e^-x=inf -> 0 (safe)
}
__device__ __forceinline__ float tanh_fast(float x) {
    x = fminf(fmaxf(x, -15.0f), 15.0f);  // avoid inf/inf
    float e = __expf(2.0f * x);
    return (e - 1.0f) / (e + 1.0f);
}

// acc[8] holds 16 fp32 accumulators (f32x2-packed, samples 2q,2q+1 in acc[q]).
// sbuf is [K][MB] in SMEM (row stride MB=16 floats, 64B aligned).
// wT is [K][G3] in GMEM; lane-coalesced at fixed k.
__device__ __forceinline__ void accum(unsigned long long acc[8],
                                      const float* __restrict__ wT,
                                      const float* sbuf, int g, int K) {
#pragma unroll 4
    for (int k = 0; k < K; k++) {
        unsigned long long w2 = pack2(wT[k * G3 + g]);
        const ulonglong2* hp = reinterpret_cast<const ulonglong2*>(sbuf + k * MB);
        ulonglong2 p0 = hp[0];
        ulonglong2 p1 = hp[1];
        fma2(acc[0], w2, p0.x); fma2(acc[1], w2, p0.y);
        fma2(acc[2], w2, p1.x); fma2(acc[3], w2, p1.y);
        ulonglong2 p2 = hp[2];
        ulonglong2 p3 = hp[3];
        fma2(acc[4], w2, p2.x); fma2(acc[5], w2, p2.y);
        fma2(acc[6], w2, p3.x); fma2(acc[7], w2, p3.y);
    }
}

// SMEM float offsets (all 16B aligned)
#define OFF_H1   0        // 128*16  = 2048
#define OFF_H2   2048     // 128*16  = 2048
#define OFF_X    4096     // 16*16   = 256
#define OFF_SG   4352     // 256*17  = 4352   (r,z pre-activations, pad 17)
#define OFF_SINN 8704     // 128*17  = 2176
#define OFF_SHN  10880    // 128*17  = 2176
#define SMEM_FLOATS 13056
#define SMEM_BYTES (SMEM_FLOATS * 4)

__device__ __forceinline__ void store_gates(const unsigned long long ai[8],
                                            const unsigned long long ah[8],
                                            int g, float* sg, float* sinn, float* shn) {
    if (g < 256) {
        float* row = sg + g * 17;
#pragma unroll
        for (int q = 0; q < 8; q++) {
            float2 a = unpack2(ai[q]);
            float2 h = unpack2(ah[q]);
            row[2 * q]     = a.x + h.x;
            row[2 * q + 1] = a.y + h.y;
        }
    } else {
        float* ri = sinn + (g - 256) * 17;
        float* rh = shn  + (g - 256) * 17;
#pragma unroll
        for (int q = 0; q < 8; q++) {
            float2 a = unpack2(ai[q]);
            float2 h = unpack2(ah[q]);
            ri[2 * q]     = a.x;
            ri[2 * q + 1] = a.y;
            rh[2 * q]     = h.x;
            rh[2 * q + 1] = h.y;
        }
    }
}

__device__ __forceinline__ void h_update(float* h, const float* sg,
                                         const float* sinn, const float* shn, int tid) {
    for (int idx = tid; idx < HID * MB; idx += G3) {
        int m = idx & (MB - 1);
        int j = idx >> 4;
        float r = sigf(sg[j * 17 + m]);
        float z = sigf(sg[(128 + j) * 17 + m]);
        float n = tanh_fast(sinn[j * 17 + m] + r * shn[j * 17 + m]);
        float ho = h[j * MB + m];
        h[j * MB + m] = n + z * (ho - n);
    }
}

// ---- prep: transpose weights into [k][g] ----------------------------------
__global__ void prep_kernel(const float* __restrict__ w_ih1,
                            const float* __restrict__ w_hh1,
                            const float* __restrict__ w_ih2,
                            const float* __restrict__ w_hh2) {
    int idx = blockIdx.x * blockDim.x + threadIdx.x;
    if (idx < 6144) {                 // w_ih1: (384,16)
        int g = idx >> 4, i = idx & 15;
        g_wih1T[i * G3 + g] = w_ih1[idx];
        return;
    }
    idx -= 6144;
    if (idx < 49152) {                // w_hh1: (384,128)
        int g = idx >> 7, k = idx & 127;
        g_whh1T[k * G3 + g] = w_hh1[idx];
        return;
    }
    idx -= 49152;
    if (idx < 49152) {                // w_ih2: (384,128)
        int g = idx >> 7, k = idx & 127;
        g_wih2T[k * G3 + g] = w_ih2[idx];
        return;
    }
    idx -= 49152;
    if (idx < 49152) {                // w_hh2: (384,128)
        int g = idx >> 7, k = idx & 127;
        g_whh2T[k * G3 + g] = w_hh2[idx];
    }
}

// ---- main fused GRU kernel ------------------------------------------------
__global__ __launch_bounds__(G3, 2)
void gru_kernel(const float* __restrict__ x,
                const float* __restrict__ b_ih1, const float* __restrict__ b_hh1,
                const float* __restrict__ b_ih2, const float* __restrict__ b_hh2,
                const float* __restrict__ fc_w,  const float* __restrict__ fc_b,
                float* __restrict__ out) {
    extern __shared__ float sm[];
    float* h1   = sm + OFF_H1;
    float* h2   = sm + OFF_H2;
    float* xs   = sm + OFF_X;
    float* sg   = sm + OFF_SG;
    float* sinn = sm + OFF_SINN;
    float* shn  = sm + OFF_SHN;

    const int tid = threadIdx.x;
    const int b0  = blockIdx.x * MB;

    // zero h1, h2
    for (int i = tid; i < 4096; i += G3) sm[i] = 0.0f;

    // x features for t=0: xfeat[m][i] = x[b, i>>3, t*8 + (i&7)]
    if (tid < 256) {
        int m = tid >> 4, i = tid & 15;
        xs[i * MB + m] = x[(b0 + m) * 2048 + (i >> 3) * 1024 + (i & 7)];
    }

    // per-thread (gate-row) biases, packed
    const unsigned long long bi1p = pack2(b_ih1[tid]);
    const unsigned long long bh1p = pack2(b_hh1[tid]);
    const unsigned long long bi2p = pack2(b_ih2[tid]);
    const unsigned long long bh2p = pack2(b_hh2[tid]);

    __syncthreads();

    for (int t = 0; t < LSEQ; t++) {
        // ---- layer 1 gates ----
        unsigned long long ai[8], ah[8];
#pragma unroll
        for (int q = 0; q < 8; q++) { ai[q] = bi1p; ah[q] = bh1p; }
        accum(ai, g_wih1T, xs, tid, 16);
        accum(ah, g_whh1T, h1, tid, HID);
        store_gates(ai, ah, tid, sg, sinn, shn);
        __syncthreads();

        h_update(h1, sg, sinn, shn, tid);
        __syncthreads();

        // ---- layer 2 gates (input = new h1) ----
#pragma unroll
        for (int q = 0; q < 8; q++) { ai[q] = bi2p; ah[q] = bh2p; }
        accum(ai, g_wih2T, h1, tid, HID);
        accum(ah, g_whh2T, h2, tid, HID);
        store_gates(ai, ah, tid, sg, sinn, shn);
        __syncthreads();

        h_update(h2, sg, sinn, shn, tid);
        // prefetch x for next step (distinct region from gates; after sync b
        // of this step nobody reads old xs)
        if (t + 1 < LSEQ && tid < 256) {
            int m = tid >> 4, i = tid & 15;
            xs[i * MB + m] = x[(b0 + m) * 2048 + (i >> 3) * 1024 + (t + 1) * 8 + (i & 7)];
        }
        __syncthreads();
    }

    // ---- FC head: out[b0+m][c] = fc_b[c] + fc_w[c,:] . h2[m,:] ----
    {
        int m = tid / NCLS;
        int c = tid - m * NCLS;   // tid<384 -> m<16
        float acc = fc_b[c];
#pragma unroll 4
        for (int j = 0; j < HID; j++)
            acc = fmaf(fc_w[c * HID + j], h2[j * MB + m], acc);
        out[(b0 + m) * NCLS + c] = acc;
    }
}

// ---------------------------------------------------------------------------
extern "C" void kernel_launch(void* const* d_in, const int* in_sizes, int n_in,
                              void* d_out, int out_size) {
    const float* x     = (const float*)d_in[0];
    const float* w_ih1 = (const float*)d_in[1];
    const float* w_hh1 = (const float*)d_in[2];
    const float* b_ih1 = (const float*)d_in[3];
    const float* b_hh1 = (const float*)d_in[4];
    const float* w_ih2 = (const float*)d_in[5];
    const float* w_hh2 = (const float*)d_in[6];
    const float* b_ih2 = (const float*)d_in[7];
    const float* b_hh2 = (const float*)d_in[8];
    const float* fc_w  = (const float*)d_in[9];
    const float* fc_b  = (const float*)d_in[10];
    float* out = (float*)d_out;

    cudaFuncSetAttribute(gru_kernel,
                         cudaFuncAttributeMaxDynamicSharedMemorySize, SMEM_BYTES);

    prep_kernel<<<(153600 + 255) / 256, 256>>>(w_ih1, w_hh1, w_ih2, w_hh2);
    gru_kernel<<<4096 / MB, G3, SMEM_BYTES>>>(x, b_ih1, b_hh1, b_ih2, b_hh2,
                                              fc_w, fc_b, out);
}

// round 3
// speedup vs baseline: 1.1879x; 1.1879x over previous
#include <cuda_runtime.h>

// ---------------------------------------------------------------------------
// GRU_23407571764060: 2-layer GRU (B=4096, L=128, in=16, hid=128) + FC(128->24)
//
// R3 strategy (vs R2): raise fma:LDS ratio. Each thread now computes
// 2 gate rows x 8 samples (was 1 row x 16). Per k: 1 LDG.64 (row-pair weights,
// straight out of the existing [k][g] transposed layout) + 2 LDS.128 + 8 FFMA2.
// LDS traffic halves; kernel becomes FMA-pipe bound (~38.4K cyc/SM/step floor).
// ---------------------------------------------------------------------------

#define MB    16      // samples per CTA
#define G3    384     // 3*HIDDEN gate rows
#define HID   128
#define LSEQ  128
#define NCLS  24
#define NR2   192     // row-pairs

// transposed weight scratch ([k][g], row-pairs are adjacent float2)
__device__ float g_wih1T[16  * G3];
__device__ float g_whh1T[HID * G3];
__device__ float g_wih2T[HID * G3];
__device__ float g_whh2T[HID * G3];

// ---- f32x2 helpers --------------------------------------------------------
__device__ __forceinline__ void fma2(unsigned long long& acc,
                                     unsigned long long a,
                                     unsigned long long b) {
    asm("fma.rn.f32x2 %0, %1, %2, %0;" : "+l"(acc) : "l"(a), "l"(b));
}
__device__ __forceinline__ unsigned long long pack2(float x) {
    unsigned long long r;
    unsigned u = __float_as_uint(x);
    asm("mov.b64 %0, {%1, %1};" : "=l"(r) : "r"(u));
    return r;
}

__device__ __forceinline__ float sigf(float x) {
    return 1.0f / (1.0f + __expf(-x));
}
__device__ __forceinline__ float tanh_fast(float x) {
    x = fminf(fmaxf(x, -15.0f), 15.0f);
    float e = __expf(2.0f * x);
    return (e - 1.0f) / (e + 1.0f);
}

// acc[0..3]: row 2*r2,   samples mh*8 + {0..7} (f32x2-packed pairs)
// acc[4..7]: row 2*r2+1, same samples
// wp = (const float2*)wT : wp[k*NR2 + r2] = (w[2r2][k], w[2r2+1][k])
// sbuf is [K][MB] in SMEM.
__device__ __forceinline__ void accum2(unsigned long long acc[8],
                                       const float2* __restrict__ wp,
                                       const float* sbuf, int r2, int mh, int K) {
#pragma unroll 4
    for (int k = 0; k < K; k++) {
        float2 w = wp[k * NR2 + r2];                       // LDG.64, 1 line/warp
        unsigned long long wa = pack2(w.x);
        unsigned long long wb = pack2(w.y);
        const ulonglong2* hp =
            reinterpret_cast<const ulonglong2*>(sbuf + k * MB + mh * 8);
        ulonglong2 p0 = hp[0];                             // LDS.128
        ulonglong2 p1 = hp[1];                             // LDS.128
        fma2(acc[0], wa, p0.x); fma2(acc[1], wa, p0.y);
        fma2(acc[2], wa, p1.x); fma2(acc[3], wa, p1.y);
        fma2(acc[4], wb, p0.x); fma2(acc[5], wb, p0.y);
        fma2(acc[6], wb, p1.x); fma2(acc[7], wb, p1.y);
    }
}

// SMEM float offsets
#define OFF_H1   0        // 128*16 = 2048
#define OFF_H2   2048     // 2048
#define OFF_X    4096     // 256
#define OFF_RZ   4352     // 256*18 = 4608  (r,z pre-activations, stride 18)
#define OFF_INN  8960     // 128*18 = 2304
#define OFF_HN   11264    // 2304
#define SMEM_FLOATS 13568
#define SMEM_BYTES (SMEM_FLOATS * 4)
#define GST 18            // gate-row stride (floats)

__device__ __forceinline__ void store_rows(const unsigned long long acc[8],
                                           float* buf0, float* buf1) {
#pragma unroll
    for (int q = 0; q < 4; q++) {
        *reinterpret_cast<unsigned long long*>(buf0 + 2 * q) = acc[q];       // STS.64
        *reinterpret_cast<unsigned long long*>(buf1 + 2 * q) = acc[4 + q];
    }
}

__device__ __forceinline__ void h_update(float* h, const float* srz,
                                         const float* sinn, const float* shn, int tid) {
    for (int idx = tid; idx < HID * MB; idx += G3) {
        int m = idx & (MB - 1);
        int j = idx >> 4;
        float r = sigf(srz[j * GST + m]);
        float z = sigf(srz[(128 + j) * GST + m]);
        float n = tanh_fast(sinn[j * GST + m] + r * shn[j * GST + m]);
        float ho = h[j * MB + m];
        h[j * MB + m] = n + z * (ho - n);
    }
}

// ---- prep: transpose weights into [k][g] (row-pairs adjacent) -------------
__global__ void prep_kernel(const float* __restrict__ w_ih1,
                            const float* __restrict__ w_hh1,
                            const float* __restrict__ w_ih2,
                            const float* __restrict__ w_hh2) {
    int idx = blockIdx.x * blockDim.x + threadIdx.x;
    if (idx < 6144) {                 // w_ih1: (384,16)
        int g = idx >> 4, i = idx & 15;
        g_wih1T[i * G3 + g] = w_ih1[idx];
        return;
    }
    idx -= 6144;
    if (idx < 49152) {                // w_hh1: (384,128)
        int g = idx >> 7, k = idx & 127;
        g_whh1T[k * G3 + g] = w_hh1[idx];
        return;
    }
    idx -= 49152;
    if (idx < 49152) {                // w_ih2
        int g = idx >> 7, k = idx & 127;
        g_wih2T[k * G3 + g] = w_ih2[idx];
        return;
    }
    idx -= 49152;
    if (idx < 49152) {                // w_hh2
        int g = idx >> 7, k = idx & 127;
        g_whh2T[k * G3 + g] = w_hh2[idx];
    }
}

// ---- main fused GRU kernel ------------------------------------------------
__global__ __launch_bounds__(G3, 2)
void gru_kernel(const float* __restrict__ x,
                const float* __restrict__ b_ih1, const float* __restrict__ b_hh1,
                const float* __restrict__ b_ih2, const float* __restrict__ b_hh2,
                const float* __restrict__ fc_w,  const float* __restrict__ fc_b,
                float* __restrict__ out) {
    extern __shared__ float sm[];
    float* h1   = sm + OFF_H1;
    float* h2   = sm + OFF_H2;
    float* xs   = sm + OFF_X;
    float* srz  = sm + OFF_RZ;
    float* sinn = sm + OFF_INN;
    float* shn  = sm + OFF_HN;

    const int tid = threadIdx.x;
    const int mh  = tid & 1;          // sample half (8 samples)
    const int r2  = tid >> 1;         // row-pair id [0,192)
    const int b0  = blockIdx.x * MB;

    const float2* w1p  = reinterpret_cast<const float2*>(g_wih1T);
    const float2* wh1p = reinterpret_cast<const float2*>(g_whh1T);
    const float2* wi2p = reinterpret_cast<const float2*>(g_wih2T);
    const float2* wh2p = reinterpret_cast<const float2*>(g_whh2T);

    // zero h1, h2
    for (int i = tid; i < 4096; i += G3) sm[i] = 0.0f;

    // x features for t=0
    if (tid < 256) {
        int m = tid >> 4, i = tid & 15;
        xs[i * MB + m] = x[(b0 + m) * 2048 + (i >> 3) * 1024 + (i & 7)];
    }

    // per-thread biases (2 rows)
    const int row0 = 2 * r2, row1 = 2 * r2 + 1;
    const float bi1_0 = b_ih1[row0], bi1_1 = b_ih1[row1];
    const float bh1_0 = b_hh1[row0], bh1_1 = b_hh1[row1];
    const float bi2_0 = b_ih2[row0], bi2_1 = b_ih2[row1];
    const float bh2_0 = b_hh2[row0], bh2_1 = b_hh2[row1];

    const bool is_rz = (r2 < 128);    // warps 0-7 rz, warps 8-11 n (uniform)
    float* g0 = is_rz ? (srz + row0 * GST + mh * 8)
                      : (sinn + (row0 - 256) * GST + mh * 8);
    float* g1 = is_rz ? (srz + row1 * GST + mh * 8)
                      : (sinn + (row1 - 256) * GST + mh * 8);
    float* n0 = shn + (row0 - 256) * GST + mh * 8;   // only used when !is_rz
    float* n1 = shn + (row1 - 256) * GST + mh * 8;

    __syncthreads();

    for (int t = 0; t < LSEQ; t++) {
        // ---- layer 1 gates ----
        if (is_rz) {
            unsigned long long a[8];
            unsigned long long b0p = pack2(bi1_0 + bh1_0);
            unsigned long long b1p = pack2(bi1_1 + bh1_1);
#pragma unroll
            for (int q = 0; q < 4; q++) { a[q] = b0p; a[4 + q] = b1p; }
            accum2(a, w1p, xs, r2, mh, 16);
            accum2(a, wh1p, h1, r2, mh, HID);
            store_rows(a, g0, g1);
        } else {
            unsigned long long a[8];
            unsigned long long b0p = pack2(bi1_0), b1p = pack2(bi1_1);
#pragma unroll
            for (int q = 0; q < 4; q++) { a[q] = b0p; a[4 + q] = b1p; }
            accum2(a, w1p, xs, r2, mh, 16);
            store_rows(a, g0, g1);                    // inn
            b0p = pack2(bh1_0); b1p = pack2(bh1_1);
#pragma unroll
            for (int q = 0; q < 4; q++) { a[q] = b0p; a[4 + q] = b1p; }
            accum2(a, wh1p, h1, r2, mh, HID);
            store_rows(a, n0, n1);                    // hn
        }
        __syncthreads();

        h_update(h1, srz, sinn, shn, tid);
        __syncthreads();

        // ---- layer 2 gates (input = new h1) ----
        if (is_rz) {
            unsigned long long a[8];
            unsigned long long b0p = pack2(bi2_0 + bh2_0);
            unsigned long long b1p = pack2(bi2_1 + bh2_1);
#pragma unroll
            for (int q = 0; q < 4; q++) { a[q] = b0p; a[4 + q] = b1p; }
            accum2(a, wi2p, h1, r2, mh, HID);
            accum2(a, wh2p, h2, r2, mh, HID);
            store_rows(a, g0, g1);
        } else {
            unsigned long long a[8];
            unsigned long long b0p = pack2(bi2_0), b1p = pack2(bi2_1);
#pragma unroll
            for (int q = 0; q < 4; q++) { a[q] = b0p; a[4 + q] = b1p; }
            accum2(a, wi2p, h1, r2, mh, HID);
            store_rows(a, g0, g1);                    // inn
            b0p = pack2(bh2_0); b1p = pack2(bh2_1);
#pragma unroll
            for (int q = 0; q < 4; q++) { a[q] = b0p; a[4 + q] = b1p; }
            accum2(a, wh2p, h2, r2, mh, HID);
            store_rows(a, n0, n1);                    // hn
        }
        __syncthreads();

        h_update(h2, srz, sinn, shn, tid);
        // prefetch x for next step (xs not read until next layer-1 accum)
        if (t + 1 < LSEQ && tid < 256) {
            int m = tid >> 4, i = tid & 15;
            xs[i * MB + m] = x[(b0 + m) * 2048 + (i >> 3) * 1024 + (t + 1) * 8 + (i & 7)];
        }
        __syncthreads();
    }

    // ---- FC head ----
    {
        int m = tid / NCLS;
        int c = tid - m * NCLS;   // 16*24 = 384
        float acc = fc_b[c];
#pragma unroll 4
        for (int j = 0; j < HID; j++)
            acc = fmaf(fc_w[c * HID + j], h2[j * MB + m], acc);
        out[(b0 + m) * NCLS + c] = acc;
    }
}

// ---------------------------------------------------------------------------
extern "C" void kernel_launch(void* const* d_in, const int* in_sizes, int n_in,
                              void* d_out, int out_size) {
    const float* x     = (const float*)d_in[0];
    const float* w_ih1 = (const float*)d_in[1];
    const float* w_hh1 = (const float*)d_in[2];
    const float* b_ih1 = (const float*)d_in[3];
    const float* b_hh1 = (const float*)d_in[4];
    const float* w_ih2 = (const float*)d_in[5];
    const float* w_hh2 = (const float*)d_in[6];
    const float* b_ih2 = (const float*)d_in[7];
    const float* b_hh2 = (const float*)d_in[8];
    const float* fc_w  = (const float*)d_in[9];
    const float* fc_b  = (const float*)d_in[10];
    float* out = (float*)d_out;

    cudaFuncSetAttribute(gru_kernel,
                         cudaFuncAttributeMaxDynamicSharedMemorySize, SMEM_BYTES);

    prep_kernel<<<(153600 + 255) / 256, 256>>>(w_ih1, w_hh1, w_ih2, w_hh2);
    gru_kernel<<<4096 / MB, G3, SMEM_BYTES>>>(x, b_ih1, b_hh1, b_ih2, b_hh2,
                                              fc_w, fc_b, out);
}

// round 6
// speedup vs baseline: 3.0532x; 2.5702x over previous
#include <cuda_runtime.h>
#include <cuda_fp16.h>
#include <cstdint>

// ---------------------------------------------------------------------------
// GRU via mma.sync (HMMA, baseline PTX — tcgen05 unavailable at compute_103).
// 128 CTAs x 256 thr, 32 samples/CTA. All operands fp16 hi+lo pairs.
// Warp w owns gate rows {r,z,inn,hn}[16w..16w+15] -> warp-local GRU update.
// ---------------------------------------------------------------------------

#define HID  128
#define MB   32
#define LSEQ 128
#define NCLS 24
#define NTHR 256

// A-fragment arrays: [frag][lane] uint4, frag = mt*nkt + kt (mt: 16-row tile)
__device__ uint4 g_wih1H[24 * 32],  g_wih1L[24 * 32];    // K=16 (nkt=1)
__device__ uint4 g_whh1H[192 * 32], g_whh1L[192 * 32];   // K=128 (nkt=8)
__device__ uint4 g_wih2H[192 * 32], g_wih2L[192 * 32];
__device__ uint4 g_whh2H[192 * 32], g_whh2L[192 * 32];

// SMEM byte offsets
#define S_WI2  0         // wih2 hi frags (98304)
#define S_WH2  98304     // whh2 hi frags (98304)
#define S_H1HI 196608    // h tiles: 32 x 128 fp16, [m][k], swizzled (8192 each)
#define S_H1LO 204800
#define S_H2HI 212992
#define S_H2LO 221184
#define S_XHI  229376    // x tiles: 32 x 16 fp16 (1024 each)
#define S_XLO  230400
#define SMEM_SZ 231424

__device__ __forceinline__ uint32_t smem_u32(const void* p) {
    uint32_t a;
    asm("{ .reg .u64 t; cvta.to.shared.u64 t, %1; cvt.u32.u64 %0, t; }"
        : "=r"(a) : "l"(p));
    return a;
}
__device__ __forceinline__ void ldm2(uint32_t& r0, uint32_t& r1, uint32_t a) {
    asm volatile("ldmatrix.sync.aligned.m8n8.x2.shared.b16 {%0,%1}, [%2];"
                 : "=r"(r0), "=r"(r1) : "r"(a));
}
__device__ __forceinline__ void mmaf(float* d, const uint4& a,
                                     uint32_t b0, uint32_t b1) {
    asm volatile("mma.sync.aligned.m16n8k16.row.col.f32.f16.f16.f32 "
                 "{%0,%1,%2,%3}, {%4,%5,%6,%7}, {%8,%9}, {%0,%1,%2,%3};"
                 : "+f"(d[0]), "+f"(d[1]), "+f"(d[2]), "+f"(d[3])
                 : "r"(a.x), "r"(a.y), "r"(a.z), "r"(a.w), "r"(b0), "r"(b1));
}
__device__ __forceinline__ float sigf(float v) { return 1.f / (1.f + __expf(-v)); }
__device__ __forceinline__ float tanhf_fast(float v) {
    v = fminf(fmaxf(v, -15.f), 15.f);
    float e = __expf(2.f * v);
    return (e - 1.f) / (e + 1.f);
}

// ---- prep: pack fp32 weights into per-lane hi/lo A fragments --------------
__global__ void prep_kernel(const float* __restrict__ w_ih1,
                            const float* __restrict__ w_hh1,
                            const float* __restrict__ w_ih2,
                            const float* __restrict__ w_hh2) {
    int t = blockIdx.x * blockDim.x + threadIdx.x;
    if (t >= 600 * 32) return;
    int f = t >> 5, lane = t & 31;
    const float* W; uint4 *dh, *dl; int K, fl;
    if (f < 24)       { W = w_ih1; dh = g_wih1H; dl = g_wih1L; K = 16;  fl = f; }
    else if (f < 216) { W = w_hh1; dh = g_whh1H; dl = g_whh1L; K = 128; fl = f - 24; }
    else if (f < 408) { W = w_ih2; dh = g_wih2H; dl = g_wih2L; K = 128; fl = f - 216; }
    else              { W = w_hh2; dh = g_whh2H; dl = g_whh2L; K = 128; fl = f - 408; }
    int nkt = K >> 4;
    int mt = fl / nkt, kt = fl % nkt;
    int gid = lane >> 2, tig = lane & 3;
    int r0 = mt * 16 + gid, r1 = r0 + 8, c0 = kt * 16 + tig * 2;
    float2 v[4];
    v[0] = *(const float2*)(W + r0 * K + c0);
    v[1] = *(const float2*)(W + r1 * K + c0);
    v[2] = *(const float2*)(W + r0 * K + c0 + 8);
    v[3] = *(const float2*)(W + r1 * K + c0 + 8);
    uint4 oh, ol;
    uint32_t* ph = (uint32_t*)&oh;
    uint32_t* pl = (uint32_t*)&ol;
#pragma unroll
    for (int q = 0; q < 4; q++) {
        __half2 hi = __floats2half2_rn(v[q].x, v[q].y);
        __half2 lo = __floats2half2_rn(v[q].x - __half2float(__low2half(hi)),
                                       v[q].y - __half2float(__high2half(hi)));
        ph[q] = *(uint32_t*)&hi;
        pl[q] = *(uint32_t*)&lo;
    }
    dh[fl * 32 + lane] = oh;
    dl[fl * 32 + lane] = ol;
}

// ---- epilogue: gates -> h update -> hi/lo store ---------------------------
__device__ __forceinline__ void gru_epilogue(
    float (&ar)[4][4], float (&az)[4][4], float (&ai)[4][4], float (&ah)[4][4],
    const float* br, const float* bz, const float* bi, const float* bh,
    float* hreg, char* smem, int hiOff, int loOff, int gid, int tig, int wbase) {
#pragma unroll
    for (int nt = 0; nt < 4; nt++)
#pragma unroll
        for (int e = 0; e < 4; e++) {
            int rowi = e >> 1;
            int m = nt * 8 + tig * 2 + (e & 1);
            float r = sigf(ar[nt][e] + br[rowi]);
            float z = sigf(az[nt][e] + bz[rowi]);
            float n = tanhf_fast(ai[nt][e] + bi[rowi] + r * (ah[nt][e] + bh[rowi]));
            float h = n + z * (hreg[nt * 4 + e] - n);
            hreg[nt * 4 + e] = h;
            __half hi = __float2half_rn(h);
            __half lo = __float2half_rn(h - __half2float(hi));
            int j = wbase + gid + rowi * 8;
            int off = m * 256 + ((2 * j) ^ ((tig * 2 + (e & 1)) << 4));
            *(__half*)(smem + hiOff + off) = hi;
            *(__half*)(smem + loOff + off) = lo;
        }
}

// ---------------------------------------------------------------------------
__global__ __launch_bounds__(NTHR, 1)
void gru_mma_kernel(const float* __restrict__ x,
                    const float* __restrict__ b_ih1, const float* __restrict__ b_hh1,
                    const float* __restrict__ b_ih2, const float* __restrict__ b_hh2,
                    const float* __restrict__ fc_w,  const float* __restrict__ fc_b,
                    float* __restrict__ out) {
    extern __shared__ char smem[];
    const uint32_t sb = smem_u32(smem);
    const int tid = threadIdx.x;
    const int wid = tid >> 5, lane = tid & 31;
    const int b0 = blockIdx.x * MB;
    const int gid = lane >> 2, tig = lane & 3;
    const int lr = lane & 7, lh = (lane >> 3) & 1;
    const int xorv = lr << 4;
    const int wbase = wid * 16;

    // load layer-2 hi frags into SMEM; zero h tiles
    {
        uint4* d1 = (uint4*)(smem + S_WI2);
        uint4* d2 = (uint4*)(smem + S_WH2);
        for (int i = tid; i < 192 * 32; i += NTHR) {
            d1[i] = g_wih2H[i];
            d2[i] = g_whh2H[i];
        }
        uint4 z4 = make_uint4(0, 0, 0, 0);
        uint4* hz = (uint4*)(smem + S_H1HI);
        for (int i = tid; i < 32768 / 16; i += NTHR) hz[i] = z4;
    }
    // stage x(t=0): thread -> (m = tid>>3, feature pair p = tid&7)
    {
        int m = tid >> 3, p = tid & 7;
        const float2 v = *(const float2*)(x + (size_t)(b0 + m) * 2048 +
                                          (p >> 2) * 1024 + ((2 * p) & 7));
        __half2 hi = __floats2half2_rn(v.x, v.y);
        __half2 lo = __floats2half2_rn(v.x - __half2float(__low2half(hi)),
                                       v.y - __half2float(__high2half(hi)));
        *(__half2*)(smem + S_XHI + m * 32 + p * 4) = hi;
        *(__half2*)(smem + S_XLO + m * 32 + p * 4) = lo;
    }
    // biases (rows j0 = wbase+gid, j1 = j0+8)
    const int j0 = wbase + gid, j1 = j0 + 8;
    float b1r[2] = { b_ih1[j0] + b_hh1[j0],             b_ih1[j1] + b_hh1[j1] };
    float b1z[2] = { b_ih1[128 + j0] + b_hh1[128 + j0], b_ih1[128 + j1] + b_hh1[128 + j1] };
    float b1i[2] = { b_ih1[256 + j0],                   b_ih1[256 + j1] };
    float b1h[2] = { b_hh1[256 + j0],                   b_hh1[256 + j1] };
    float b2r[2] = { b_ih2[j0] + b_hh2[j0],             b_ih2[j1] + b_hh2[j1] };
    float b2z[2] = { b_ih2[128 + j0] + b_hh2[128 + j0], b_ih2[128 + j1] + b_hh2[128 + j1] };
    float b2i[2] = { b_ih2[256 + j0],                   b_ih2[256 + j1] };
    float b2h[2] = { b_hh2[256 + j0],                   b_hh2[256 + j1] };

    float h1reg[16], h2reg[16];
#pragma unroll
    for (int q = 0; q < 16; q++) { h1reg[q] = 0.f; h2reg[q] = 0.f; }

    uint32_t rowoff[4];
#pragma unroll
    for (int nt = 0; nt < 4; nt++) rowoff[nt] = (nt * 8 + lr) * 256;

    __syncthreads();

    float ar[4][4], az[4][4], ai[4][4], ah[4][4];

#pragma unroll 1
    for (int t = 0; t < LSEQ; t++) {
#pragma unroll
        for (int nt = 0; nt < 4; nt++)
#pragma unroll
            for (int e = 0; e < 4; e++) {
                ar[nt][e] = 0.f; az[nt][e] = 0.f; ai[nt][e] = 0.f; ah[nt][e] = 0.f;
            }
        // ---- L1: x contribution (K=16, hi/lo) ----
        {
            uint4 Ar = g_wih1H[wid * 32 + lane];
            uint4 Az = g_wih1H[(8 + wid) * 32 + lane];
            uint4 Ai = g_wih1H[(16 + wid) * 32 + lane];
            uint4 Lr = g_wih1L[wid * 32 + lane];
            uint4 Lz = g_wih1L[(8 + wid) * 32 + lane];
            uint4 Li = g_wih1L[(16 + wid) * 32 + lane];
#pragma unroll
            for (int nt = 0; nt < 4; nt++) {
                uint32_t a = sb + S_XHI + (nt * 8 + lr) * 32 + lh * 16;
                uint32_t bh0, bh1, bl0, bl1;
                ldm2(bh0, bh1, a);
                ldm2(bl0, bl1, a + (S_XLO - S_XHI));
                mmaf(ar[nt], Ar, bh0, bh1); mmaf(ar[nt], Ar, bl0, bl1); mmaf(ar[nt], Lr, bh0, bh1);
                mmaf(az[nt], Az, bh0, bh1); mmaf(az[nt], Az, bl0, bl1); mmaf(az[nt], Lz, bh0, bh1);
                mmaf(ai[nt], Ai, bh0, bh1); mmaf(ai[nt], Ai, bl0, bl1); mmaf(ai[nt], Li, bh0, bh1);
            }
        }
        // ---- L1: h1 recurrent (whh1 streamed from L2) ----
#pragma unroll 2
        for (int kt = 0; kt < 8; kt++) {
            uint4 Ar = g_whh1H[(wid * 8 + kt) * 32 + lane];
            uint4 Az = g_whh1H[((8 + wid) * 8 + kt) * 32 + lane];
            uint4 An = g_whh1H[((16 + wid) * 8 + kt) * 32 + lane];
            uint4 Lr = g_whh1L[(wid * 8 + kt) * 32 + lane];
            uint4 Lz = g_whh1L[((8 + wid) * 8 + kt) * 32 + lane];
            uint4 Ln = g_whh1L[((16 + wid) * 8 + kt) * 32 + lane];
            uint32_t kb = (uint32_t)((kt * 32 + lh * 16) ^ xorv);
#pragma unroll
            for (int nt = 0; nt < 4; nt++) {
                uint32_t a = sb + S_H1HI + rowoff[nt] + kb;
                uint32_t bh0, bh1, bl0, bl1;
                ldm2(bh0, bh1, a);
                ldm2(bl0, bl1, a + 8192);
                mmaf(ar[nt], Ar, bh0, bh1); mmaf(ar[nt], Ar, bl0, bl1); mmaf(ar[nt], Lr, bh0, bh1);
                mmaf(az[nt], Az, bh0, bh1); mmaf(az[nt], Az, bl0, bl1); mmaf(az[nt], Lz, bh0, bh1);
                mmaf(ah[nt], An, bh0, bh1); mmaf(ah[nt], An, bl0, bl1); mmaf(ah[nt], Ln, bh0, bh1);
            }
        }
        __syncthreads();                       // S1: all h1/x reads done
        gru_epilogue(ar, az, ai, ah, b1r, b1z, b1i, b1h, h1reg,
                     smem, S_H1HI, S_H1LO, gid, tig, wbase);
        if (t + 1 < LSEQ) {                    // stage x(t+1)
            int m = tid >> 3, p = tid & 7;
            const float2 v = *(const float2*)(x + (size_t)(b0 + m) * 2048 +
                                              (p >> 2) * 1024 + (t + 1) * 8 + ((2 * p) & 7));
            __half2 hi = __floats2half2_rn(v.x, v.y);
            __half2 lo = __floats2half2_rn(v.x - __half2float(__low2half(hi)),
                                           v.y - __half2float(__high2half(hi)));
            *(__half2*)(smem + S_XHI + m * 32 + p * 4) = hi;
            *(__half2*)(smem + S_XLO + m * 32 + p * 4) = lo;
        }
        __syncthreads();                       // S2: h1(t), x(t+1) visible

        // ---- L2 ----
#pragma unroll
        for (int nt = 0; nt < 4; nt++)
#pragma unroll
            for (int e = 0; e < 4; e++) {
                ar[nt][e] = 0.f; az[nt][e] = 0.f; ai[nt][e] = 0.f; ah[nt][e] = 0.f;
            }
        // wih2 @ h1 (A hi from SMEM, A lo from L2)
#pragma unroll 2
        for (int kt = 0; kt < 8; kt++) {
            const uint4* wf = (const uint4*)(smem + S_WI2);
            uint4 Ar = wf[(wid * 8 + kt) * 32 + lane];
            uint4 Az = wf[((8 + wid) * 8 + kt) * 32 + lane];
            uint4 Ai = wf[((16 + wid) * 8 + kt) * 32 + lane];
            uint4 Lr = g_wih2L[(wid * 8 + kt) * 32 + lane];
            uint4 Lz = g_wih2L[((8 + wid) * 8 + kt) * 32 + lane];
            uint4 Li = g_wih2L[((16 + wid) * 8 + kt) * 32 + lane];
            uint32_t kb = (uint32_t)((kt * 32 + lh * 16) ^ xorv);
#pragma unroll
            for (int nt = 0; nt < 4; nt++) {
                uint32_t a = sb + S_H1HI + rowoff[nt] + kb;
                uint32_t bh0, bh1, bl0, bl1;
                ldm2(bh0, bh1, a);
                ldm2(bl0, bl1, a + 8192);
                mmaf(ar[nt], Ar, bh0, bh1); mmaf(ar[nt], Ar, bl0, bl1); mmaf(ar[nt], Lr, bh0, bh1);
                mmaf(az[nt], Az, bh0, bh1); mmaf(az[nt], Az, bl0, bl1); mmaf(az[nt], Lz, bh0, bh1);
                mmaf(ai[nt], Ai, bh0, bh1); mmaf(ai[nt], Ai, bl0, bl1); mmaf(ai[nt], Li, bh0, bh1);
            }
        }
        // whh2 @ h2 (A hi from SMEM, A lo from L2)
#pragma unroll 2
        for (int kt = 0; kt < 8; kt++) {
            const uint4* wf = (const uint4*)(smem + S_WH2);
            uint4 Ar = wf[(wid * 8 + kt) * 32 + lane];
            uint4 Az = wf[((8 + wid) * 8 + kt) * 32 + lane];
            uint4 An = wf[((16 + wid) * 8 + kt) * 32 + lane];
            uint4 Lr = g_whh2L[(wid * 8 + kt) * 32 + lane];
            uint4 Lz = g_whh2L[((8 + wid) * 8 + kt) * 32 + lane];
            uint4 Ln = g_whh2L[((16 + wid) * 8 + kt) * 32 + lane];
            uint32_t kb = (uint32_t)((kt * 32 + lh * 16) ^ xorv);
#pragma unroll
            for (int nt = 0; nt < 4; nt++) {
                uint32_t a = sb + S_H2HI + rowoff[nt] + kb;
                uint32_t bh0, bh1, bl0, bl1;
                ldm2(bh0, bh1, a);
                ldm2(bl0, bl1, a + 8192);
                mmaf(ar[nt], Ar, bh0, bh1); mmaf(ar[nt], Ar, bl0, bl1); mmaf(ar[nt], Lr, bh0, bh1);
                mmaf(az[nt], Az, bh0, bh1); mmaf(az[nt], Az, bl0, bl1); mmaf(az[nt], Lz, bh0, bh1);
                mmaf(ah[nt], An, bh0, bh1); mmaf(ah[nt], An, bl0, bl1); mmaf(ah[nt], Ln, bh0, bh1);
            }
        }
        __syncthreads();                       // S3: h1/h2 reads done
        gru_epilogue(ar, az, ai, ah, b2r, b2z, b2i, b2h, h2reg,
                     smem, S_H2HI, S_H2LO, gid, tig, wbase);
        // next L1 touches only h1/x; h2 re-read after S2(t+1) — safe
    }

    // ---- FC head ----
    __syncthreads();
    float* hs = (float*)smem;                  // [32][128] fp32 over weight region
#pragma unroll
    for (int nt = 0; nt < 4; nt++)
#pragma unroll
        for (int e = 0; e < 4; e++) {
            int m = nt * 8 + tig * 2 + (e & 1);
            int j = wbase + gid + (e >> 1) * 8;
            hs[m * 128 + j] = h2reg[nt * 4 + e];
        }
    __syncthreads();
    {
        int o0 = tid * 3;
#pragma unroll
        for (int o = o0; o < o0 + 3; o++) {
            int m = o / NCLS, c = o - (o / NCLS) * NCLS;
            float acc = fc_b[c];
#pragma unroll 4
            for (int k = 0; k < HID; k++)
                acc = fmaf(fc_w[c * HID + k], hs[m * 128 + k], acc);
            out[(size_t)(b0 + m) * NCLS + c] = acc;
        }
    }
}

// ---------------------------------------------------------------------------
extern "C" void kernel_launch(void* const* d_in, const int* in_sizes, int n_in,
                              void* d_out, int out_size) {
    const float* x     = (const float*)d_in[0];
    const float* w_ih1 = (const float*)d_in[1];
    const float* w_hh1 = (const float*)d_in[2];
    const float* b_ih1 = (const float*)d_in[3];
    const float* b_hh1 = (const float*)d_in[4];
    const float* w_ih2 = (const float*)d_in[5];
    const float* w_hh2 = (const float*)d_in[6];
    const float* b_ih2 = (const float*)d_in[7];
    const float* b_hh2 = (const float*)d_in[8];
    const float* fc_w  = (const float*)d_in[9];
    const float* fc_b  = (const float*)d_in[10];
    float* out = (float*)d_out;

    cudaFuncSetAttribute(gru_mma_kernel,
                         cudaFuncAttributeMaxDynamicSharedMemorySize, SMEM_SZ);

    prep_kernel<<<75, 256>>>(w_ih1, w_hh1, w_ih2, w_hh2);
    gru_mma_kernel<<<4096 / MB, NTHR, SMEM_SZ>>>(x, b_ih1, b_hh1, b_ih2, b_hh2,
                                                 fc_w, fc_b, out);
}